// round 16
// baseline (speedup 1.0000x reference)
#include <cuda_runtime.h>
#include <cuda_bf16.h>
#include <math.h>
#include <stdint.h>

// Problem constants
#define BATCH 8
#define HGT 32
#define WID 32
#define DIM 768
#define NH 12
#define HD 64
#define LSEQ 1024
#define MROWS (BATCH*LSEQ)      // 8192
#define NQKV (3*DIM)            // 2304
#define NHEADS (BATCH*NH)       // 96

// ---------------- scratch (static device globals; no allocation) ----------------
__device__ float g_qkv[MROWS * NQKV];
__device__ float g_qf[NHEADS * LSEQ * HD];
__device__ float g_rh[NHEADS * LSEQ * 32];
__device__ float g_rw[NHEADS * LSEQ * 32];
__device__ __nv_bfloat16 g_xh[MROWS * DIM];
__device__ __nv_bfloat16 g_xl[MROWS * DIM];
__device__ __nv_bfloat16 g_wqh[NQKV * DIM];
__device__ __nv_bfloat16 g_wql[NQKV * DIM];
__device__ __nv_bfloat16 g_qh[NHEADS * LSEQ * HD];
__device__ __nv_bfloat16 g_ql[NHEADS * LSEQ * HD];
__device__ __nv_bfloat16 g_kh[NHEADS * LSEQ * HD];
__device__ __nv_bfloat16 g_kl[NHEADS * LSEQ * HD];
__device__ __nv_bfloat16 g_vth[NHEADS * HD * LSEQ];
__device__ __nv_bfloat16 g_vtl[NHEADS * HD * LSEQ];
__device__ __nv_bfloat16 g_Lh[(size_t)NHEADS * LSEQ * LSEQ];   // logit hi
__device__ __nv_bfloat16 g_Ll[(size_t)NHEADS * LSEQ * LSEQ];   // logit lo
__device__ __nv_bfloat16 g_ath[MROWS * DIM];
__device__ __nv_bfloat16 g_atl[MROWS * DIM];
__device__ __nv_bfloat16 g_wph[DIM * DIM];
__device__ __nv_bfloat16 g_wpl[DIM * DIM];

// ================= helpers ======================================================
__device__ __forceinline__ uint32_t smem_u32(const void* p) {
    uint32_t a;
    asm("{ .reg .u64 t; cvta.to.shared.u64 t, %1; cvt.u32.u64 %0, t; }"
        : "=r"(a) : "l"(p));
    return a;
}
#define LDSM_X4(r0, r1, r2, r3, addr) \
    asm volatile("ldmatrix.sync.aligned.m8n8.x4.shared.b16 {%0,%1,%2,%3}, [%4];" \
                 : "=r"(r0), "=r"(r1), "=r"(r2), "=r"(r3) : "r"(addr))
__device__ __forceinline__ void mma_bf16(float* d, const uint32_t* a,
                                         uint32_t b0, uint32_t b1) {
    asm volatile(
        "mma.sync.aligned.m16n8k16.row.col.f32.bf16.bf16.f32 "
        "{%0,%1,%2,%3}, {%4,%5,%6,%7}, {%8,%9}, {%0,%1,%2,%3};"
        : "+f"(d[0]), "+f"(d[1]), "+f"(d[2]), "+f"(d[3])
        : "r"(a[0]), "r"(a[1]), "r"(a[2]), "r"(a[3]), "r"(b0), "r"(b1));
}
__device__ __forceinline__ void split2(float v, __nv_bfloat16& h, __nv_bfloat16& l) {
    h = __float2bfloat16(v);
    l = __float2bfloat16(v - __bfloat162float(h));
}
__device__ __forceinline__ void cp16(uint32_t s, const void* g) {
    asm volatile("cp.async.cg.shared.global [%0], [%1], 16;" :: "r"(s), "l"(g));
}
#define CP_COMMIT() asm volatile("cp.async.commit_group;" ::: "memory")
#define CP_WAIT0()  asm volatile("cp.async.wait_group 0;" ::: "memory")
#define CP_WAIT1()  asm volatile("cp.async.wait_group 1;" ::: "memory")

#define SSTR 40                     // smem row stride (bf16): 80 B, ldsm conflict-free
#define TILEB (128 * SSTR * 2)      // 10240 B per 128x32 tile
#define TILEB64 (64 * SSTR * 2)     // 5120 B per 64x32 tile

__device__ __forceinline__ float fexp_neg(float x) {
    float t = fmaxf(x * 1.4426950408889634f, -126.0f);
    float fl = floorf(t);
    float f = t - fl;
    float p = 1.5403530e-4f;
    p = fmaf(p, f, 1.3333558e-3f);
    p = fmaf(p, f, 9.6181291e-3f);
    p = fmaf(p, f, 5.5504109e-2f);
    p = fmaf(p, f, 2.4022651e-1f);
    p = fmaf(p, f, 6.9314718e-1f);
    p = fmaf(p, f, 1.0f);
    int i = (int)fl;
    return p * __int_as_float((i + 127) << 23);
}

// ================= bf16 hi/lo split (elementwise) ===============================
__global__ __launch_bounds__(256) void split_bf16(
    const float4* __restrict__ X, uint32_t* __restrict__ Hi,
    uint32_t* __restrict__ Lo, int n4)
{
    int i = blockIdx.x * 256 + threadIdx.x;
    if (i >= n4) return;
    float4 v = X[i];
    __nv_bfloat16 h0, h1, h2, h3, l0, l1, l2, l3;
    split2(v.x, h0, l0); split2(v.y, h1, l1);
    split2(v.z, h2, l2); split2(v.w, h3, l3);
    __nv_bfloat162 hA = {h0, h1}, hB = {h2, h3}, lA = {l0, l1}, lB = {l2, l3};
    Hi[2 * i] = *(uint32_t*)&hA; Hi[2 * i + 1] = *(uint32_t*)&hB;
    Lo[2 * i] = *(uint32_t*)&lA; Lo[2 * i + 1] = *(uint32_t*)&lB;
}

// ======== shared compute: 3-product fragment pass over one staged buffer ========
template <int NI>
__device__ __forceinline__ void mma_pass(
    uint32_t bAh, uint32_t bAl, uint32_t bBh, uint32_t bBl,
    int wm, int wn, int lane, float acc[2][NI][4])
{
#pragma unroll
    for (int ks = 0; ks < 2; ks++) {
        const int kb = ks * 16;
        uint32_t ah[2][4], al[2][4], bf[NI / 2][4];
        const uint32_t aoff = (((lane & 15)) * SSTR + kb + ((lane >> 4) * 8)) * 2;
#pragma unroll
        for (int mi = 0; mi < 2; mi++) {
            uint32_t ab = ((wm + mi * 16) * SSTR) * 2 + aoff;
            LDSM_X4(ah[mi][0], ah[mi][1], ah[mi][2], ah[mi][3], bAh + ab);
            LDSM_X4(al[mi][0], al[mi][1], al[mi][2], al[mi][3], bAl + ab);
        }
        const uint32_t boff =
            (((lane & 7) + (((lane >> 4) & 1) * 8)) * SSTR + kb + (((lane >> 3) & 1) * 8)) * 2;
#pragma unroll
        for (int ng = 0; ng < NI / 2; ng++) {
            uint32_t bb = ((wn + ng * 16) * SSTR) * 2 + boff;
            LDSM_X4(bf[ng][0], bf[ng][1], bf[ng][2], bf[ng][3], bBh + bb);
        }
#pragma unroll
        for (int mi = 0; mi < 2; mi++)
#pragma unroll
            for (int ng = 0; ng < NI / 2; ng++) {
                mma_bf16(acc[mi][2 * ng + 0], ah[mi], bf[ng][0], bf[ng][1]);
                mma_bf16(acc[mi][2 * ng + 1], ah[mi], bf[ng][2], bf[ng][3]);
                mma_bf16(acc[mi][2 * ng + 0], al[mi], bf[ng][0], bf[ng][1]);
                mma_bf16(acc[mi][2 * ng + 1], al[mi], bf[ng][2], bf[ng][3]);
            }
#pragma unroll
        for (int ng = 0; ng < NI / 2; ng++) {
            uint32_t bb = ((wn + ng * 16) * SSTR) * 2 + boff;
            LDSM_X4(bf[ng][0], bf[ng][1], bf[ng][2], bf[ng][3], bBl + bb);
        }
#pragma unroll
        for (int mi = 0; mi < 2; mi++)
#pragma unroll
            for (int ng = 0; ng < NI / 2; ng++) {
                mma_bf16(acc[mi][2 * ng + 0], ah[mi], bf[ng][0], bf[ng][1]);
                mma_bf16(acc[mi][2 * ng + 1], ah[mi], bf[ng][2], bf[ng][3]);
            }
    }
}

// ================= HMMA NT GEMM (4-tile staging, cp.async double-buffer) ========
extern __shared__ __align__(16) char dsm[];

__global__ __launch_bounds__(256, 2) void mma_gemm(
    const __nv_bfloat16* __restrict__ Ah, const __nv_bfloat16* __restrict__ Al,
    const __nv_bfloat16* __restrict__ Bh, const __nv_bfloat16* __restrict__ Bl,
    const float* __restrict__ bias, float* __restrict__ C, int Nd, int Kc)
{
    const int tid = threadIdx.x;
    const int lane = tid & 31, wid = tid >> 5;
    const int wm = (wid & 3) * 32;
    const int wn = (wid >> 2) * 64;
    const int m0 = blockIdx.y * 128, n0 = blockIdx.x * 128;

    const uint32_t base = smem_u32(dsm);
    const int r0 = tid >> 2, c0 = (tid & 3) * 8;
    const int r1 = (tid + 256) >> 2, c1 = ((tid + 256) & 3) * 8;
    const uint32_t s0 = (r0 * SSTR + c0) * 2, s1 = (r1 * SSTR + c1) * 2;

    const int kt = Kc / 32;

    float acc[2][8][4];
#pragma unroll
    for (int mi = 0; mi < 2; mi++)
#pragma unroll
        for (int ni = 0; ni < 8; ni++)
#pragma unroll
            for (int j = 0; j < 4; j++) acc[mi][ni][j] = 0.f;

    auto issue = [&](int k0, int buf) {
        uint32_t bb = base + buf * 4 * TILEB;
        cp16(bb + 0 * TILEB + s0, Ah + (size_t)(m0 + r0) * Kc + k0 + c0);
        cp16(bb + 0 * TILEB + s1, Ah + (size_t)(m0 + r1) * Kc + k0 + c1);
        cp16(bb + 1 * TILEB + s0, Al + (size_t)(m0 + r0) * Kc + k0 + c0);
        cp16(bb + 1 * TILEB + s1, Al + (size_t)(m0 + r1) * Kc + k0 + c1);
        cp16(bb + 2 * TILEB + s0, Bh + (size_t)(n0 + r0) * Kc + k0 + c0);
        cp16(bb + 2 * TILEB + s1, Bh + (size_t)(n0 + r1) * Kc + k0 + c1);
        cp16(bb + 3 * TILEB + s0, Bl + (size_t)(n0 + r0) * Kc + k0 + c0);
        cp16(bb + 3 * TILEB + s1, Bl + (size_t)(n0 + r1) * Kc + k0 + c1);
        CP_COMMIT();
    };

    issue(0, 0);
    for (int it = 0; it < kt; it++) {
        if (it + 1 < kt) { issue((it + 1) * 32, (it + 1) & 1); CP_WAIT1(); }
        else CP_WAIT0();
        __syncthreads();
        uint32_t bb = base + (it & 1) * 4 * TILEB;
        mma_pass<8>(bb, bb + TILEB, bb + 2 * TILEB, bb + 3 * TILEB,
                    wm, wn, lane, acc);
        __syncthreads();
    }

#pragma unroll
    for (int mi = 0; mi < 2; mi++)
#pragma unroll
        for (int ni = 0; ni < 8; ni++) {
            int row = m0 + wm + mi * 16 + (lane >> 2);
            int col = n0 + wn + ni * 8 + (lane & 3) * 2;
            float b0 = bias[col], b1 = bias[col + 1];
            float2 o0 = {acc[mi][ni][0] + b0, acc[mi][ni][1] + b1};
            float2 o1 = {acc[mi][ni][2] + b0, acc[mi][ni][3] + b1};
            *(float2*)&C[(size_t)row * Nd + col] = o0;
            *(float2*)&C[(size_t)(row + 8) * Nd + col] = o1;
        }
}

// ================= flash attention: scores+softmax+AV fused =====================
// grid (m-tiles=8, heads=96), 256 threads, dyn smem 80 KB.
// Pass 1: Q resident; loop K-tiles; S-MMA; running row max/sum; spill logits bf16
//         hi/lo. Pass 2: reload logit tiles (L2-hot), exp in-place, AV-MMA.
__device__ __forceinline__ void xform_cell(char* hp, char* lp, float m, float ri) {
    uint4 hv = *(uint4*)hp, lv = *(uint4*)lp;
    uint32_t* h = (uint32_t*)&hv;
    uint32_t* l = (uint32_t*)&lv;
#pragma unroll
    for (int i = 0; i < 4; i++) {
        __nv_bfloat162 h2 = *(__nv_bfloat162*)&h[i];
        __nv_bfloat162 l2 = *(__nv_bfloat162*)&l[i];
        float a = __bfloat162float(h2.x) + __bfloat162float(l2.x);
        float c = __bfloat162float(h2.y) + __bfloat162float(l2.y);
        float pa = fexp_neg(a - m) * ri;
        float pc = fexp_neg(c - m) * ri;
        __nv_bfloat16 ha, la, hc, lc;
        split2(pa, ha, la); split2(pc, hc, lc);
        __nv_bfloat162 ho = {ha, hc}, lo = {la, lc};
        h[i] = *(uint32_t*)&ho; l[i] = *(uint32_t*)&lo;
    }
    *(uint4*)hp = hv; *(uint4*)lp = lv;
}

__global__ __launch_bounds__(256, 2) void flash_attn(
    const __nv_bfloat16* __restrict__ Qh, const __nv_bfloat16* __restrict__ Ql,
    const __nv_bfloat16* __restrict__ Kh, const __nv_bfloat16* __restrict__ Kl,
    const __nv_bfloat16* __restrict__ Vth, const __nv_bfloat16* __restrict__ Vtl,
    const float* __restrict__ RH, const float* __restrict__ RW,
    __nv_bfloat16* __restrict__ Lh, __nv_bfloat16* __restrict__ Ll,
    __nv_bfloat16* __restrict__ OutH, __nv_bfloat16* __restrict__ OutL)
{
    __shared__ float m_s[128], s_s[128], tmx[128][2], tsum[128][2];
    const int tid = threadIdx.x;
    const int lane = tid & 31, wid = tid >> 5;
    const int wm = (wid & 3) * 32;
    const int wnh = wid >> 2;
    const int bn = blockIdx.y, b = bn / NH, n = bn % NH;
    const int m0 = blockIdx.x * 128;

    const size_t hb = (size_t)bn * LSEQ * HD;
    const __nv_bfloat16* Qhp = Qh + hb; const __nv_bfloat16* Qlp = Ql + hb;
    const __nv_bfloat16* Khp = Kh + hb; const __nv_bfloat16* Klp = Kl + hb;
    const __nv_bfloat16* Vhp = Vth + (size_t)bn * HD * LSEQ;
    const __nv_bfloat16* Vlp = Vtl + (size_t)bn * HD * LSEQ;
    __nv_bfloat16* LhB = Lh + (size_t)bn * LSEQ * LSEQ;
    __nv_bfloat16* LlB = Ll + (size_t)bn * LSEQ * LSEQ;

    const uint32_t base = smem_u32(dsm);
    const int r0 = tid >> 2, c0 = (tid & 3) * 8;     // r0: 0..63
    const uint32_t s0 = (r0 * SSTR + c0) * 2;
    const uint32_t s1 = s0 + 64 * SSTR * 2;          // rows 64..127
    const uint32_t KB = base + 40960;

    if (tid < 128) { m_s[tid] = -1e30f; s_s[tid] = 0.f; }

    // stage Q (resident: Qh0@0, Ql0@10240, Qh1@20480, Ql1@30720)
#pragma unroll
    for (int qc = 0; qc < 2; qc++) {
        uint32_t qb = base + qc * 20480;
        cp16(qb + s0, Qhp + (size_t)(m0 + r0) * HD + qc * 32 + c0);
        cp16(qb + s1, Qhp + (size_t)(m0 + r0 + 64) * HD + qc * 32 + c0);
        cp16(qb + 10240 + s0, Qlp + (size_t)(m0 + r0) * HD + qc * 32 + c0);
        cp16(qb + 10240 + s1, Qlp + (size_t)(m0 + r0 + 64) * HD + qc * 32 + c0);
    }
    CP_COMMIT();

    auto issueK = [&](int g, int buf) {
        int n0g = (g >> 1) * 128, kc = (g & 1) * 32;
        uint32_t bb = KB + buf * 20480;
        cp16(bb + s0, Khp + (size_t)(n0g + r0) * HD + kc + c0);
        cp16(bb + s1, Khp + (size_t)(n0g + r0 + 64) * HD + kc + c0);
        cp16(bb + 10240 + s0, Klp + (size_t)(n0g + r0) * HD + kc + c0);
        cp16(bb + 10240 + s1, Klp + (size_t)(n0g + r0 + 64) * HD + kc + c0);
        CP_COMMIT();
    };

    float acc[2][8][4];
#pragma unroll
    for (int mi = 0; mi < 2; mi++)
#pragma unroll
        for (int ni = 0; ni < 8; ni++)
#pragma unroll
            for (int j = 0; j < 4; j++) acc[mi][ni][j] = 0.f;

    issueK(0, 0);

    // =========================== PASS 1 ===========================
    for (int g = 0; g < 16; g++) {
        if (g + 1 < 16) { issueK(g + 1, (g + 1) & 1); CP_WAIT1(); }
        else CP_WAIT0();
        __syncthreads();
        uint32_t qb = base + (g & 1) * 20480;   // Q chunk kc = g&1
        uint32_t kb = KB + (g & 1) * 20480;
        mma_pass<8>(qb, qb + 10240, kb, kb + 10240, wm, wnh * 64, lane, acc);

        if ((g & 1) == 0) { __syncthreads(); continue; }

        // ---- epilogue for n-tile nt ----
        const int nt = g >> 1;
        const int n0g = nt * 128;
        const int colg = n0g + wnh * 64 + (lane & 3) * 2;
        float mxA[2], mxB[2];
#pragma unroll
        for (int mi = 0; mi < 2; mi++) {
            int rowA = m0 + wm + mi * 16 + (lane >> 2);
            const float* rh0 = RH + ((size_t)bn * LSEQ + rowA) * 32;
            const float* rw0 = RW + ((size_t)bn * LSEQ + rowA) * 32;
            const float* rh1 = rh0 + 256;
            const float* rw1 = rw0 + 256;
            float ma = -1e30f, mb = -1e30f;
#pragma unroll
            for (int ni = 0; ni < 8; ni++) {
                int col = colg + ni * 8;
                float bh0 = rh0[col >> 5], bh1 = rh1[col >> 5];
                int cw = col & 31;
                acc[mi][ni][0] = fmaf(acc[mi][ni][0], 0.125f, bh0 + rw0[cw]);
                acc[mi][ni][1] = fmaf(acc[mi][ni][1], 0.125f, bh0 + rw0[cw + 1]);
                acc[mi][ni][2] = fmaf(acc[mi][ni][2], 0.125f, bh1 + rw1[cw]);
                acc[mi][ni][3] = fmaf(acc[mi][ni][3], 0.125f, bh1 + rw1[cw + 1]);
                ma = fmaxf(ma, fmaxf(acc[mi][ni][0], acc[mi][ni][1]));
                mb = fmaxf(mb, fmaxf(acc[mi][ni][2], acc[mi][ni][3]));
            }
            mxA[mi] = ma; mxB[mi] = mb;
        }
#pragma unroll
        for (int off = 1; off <= 2; off <<= 1) {
            mxA[0] = fmaxf(mxA[0], __shfl_xor_sync(0xffffffffu, mxA[0], off));
            mxA[1] = fmaxf(mxA[1], __shfl_xor_sync(0xffffffffu, mxA[1], off));
            mxB[0] = fmaxf(mxB[0], __shfl_xor_sync(0xffffffffu, mxB[0], off));
            mxB[1] = fmaxf(mxB[1], __shfl_xor_sync(0xffffffffu, mxB[1], off));
        }
        if ((lane & 3) == 0) {
            int lr = wm + (lane >> 2);
            tmx[lr][wnh] = mxA[0];       tmx[lr + 8][wnh] = mxB[0];
            tmx[lr + 16][wnh] = mxA[1];  tmx[lr + 24][wnh] = mxB[1];
        }
        __syncthreads();
        float sA[2] = {0.f, 0.f}, sB[2] = {0.f, 0.f};
#pragma unroll
        for (int mi = 0; mi < 2; mi++) {
            int lr = wm + mi * 16 + (lane >> 2);
            float mnA = fmaxf(m_s[lr], fmaxf(tmx[lr][0], tmx[lr][1]));
            float mnB = fmaxf(m_s[lr + 8], fmaxf(tmx[lr + 8][0], tmx[lr + 8][1]));
#pragma unroll
            for (int ni = 0; ni < 8; ni++) {
                sA[mi] += fexp_neg(acc[mi][ni][0] - mnA) + fexp_neg(acc[mi][ni][1] - mnA);
                sB[mi] += fexp_neg(acc[mi][ni][2] - mnB) + fexp_neg(acc[mi][ni][3] - mnB);
            }
        }
#pragma unroll
        for (int off = 1; off <= 2; off <<= 1) {
            sA[0] += __shfl_xor_sync(0xffffffffu, sA[0], off);
            sA[1] += __shfl_xor_sync(0xffffffffu, sA[1], off);
            sB[0] += __shfl_xor_sync(0xffffffffu, sB[0], off);
            sB[1] += __shfl_xor_sync(0xffffffffu, sB[1], off);
        }
        if ((lane & 3) == 0) {
            int lr = wm + (lane >> 2);
            tsum[lr][wnh] = sA[0];       tsum[lr + 8][wnh] = sB[0];
            tsum[lr + 16][wnh] = sA[1];  tsum[lr + 24][wnh] = sB[1];
        }
        __syncthreads();
        if (tid < 128) {
            float mo = m_s[tid];
            float mn = fmaxf(mo, fmaxf(tmx[tid][0], tmx[tid][1]));
            s_s[tid] = s_s[tid] * fexp_neg(mo - mn) + tsum[tid][0] + tsum[tid][1];
            m_s[tid] = mn;
        }
        // spill logits (bf16 hi/lo) and zero acc
#pragma unroll
        for (int mi = 0; mi < 2; mi++)
#pragma unroll
            for (int ni = 0; ni < 8; ni++) {
                int rowA = m0 + wm + mi * 16 + (lane >> 2);
                int col = colg + ni * 8;
                __nv_bfloat16 h0, l0, h1, l1;
                split2(acc[mi][ni][0], h0, l0); split2(acc[mi][ni][1], h1, l1);
                __nv_bfloat162 hp = {h0, h1}, lp = {l0, l1};
                *(uint32_t*)&LhB[(size_t)rowA * LSEQ + col] = *(uint32_t*)&hp;
                *(uint32_t*)&LlB[(size_t)rowA * LSEQ + col] = *(uint32_t*)&lp;
                split2(acc[mi][ni][2], h0, l0); split2(acc[mi][ni][3], h1, l1);
                __nv_bfloat162 hp2 = {h0, h1}, lp2 = {l0, l1};
                *(uint32_t*)&LhB[(size_t)(rowA + 8) * LSEQ + col] = *(uint32_t*)&hp2;
                *(uint32_t*)&LlB[(size_t)(rowA + 8) * LSEQ + col] = *(uint32_t*)&lp2;
                acc[mi][ni][0] = acc[mi][ni][1] = acc[mi][ni][2] = acc[mi][ni][3] = 0.f;
            }
        __syncthreads();
    }

    // =========================== PASS 2 ===========================
    if (tid < 128) s_s[tid] = 1.0f / s_s[tid];
    __syncthreads();

    const uint32_t VB = base + 40960;
    auto issueL = [&](int it, int buf) {
        uint32_t bb = base + buf * 20480;
        int kc = it * 32;
        cp16(bb + s0, LhB + (size_t)(m0 + r0) * LSEQ + kc + c0);
        cp16(bb + s1, LhB + (size_t)(m0 + r0 + 64) * LSEQ + kc + c0);
        cp16(bb + 10240 + s0, LlB + (size_t)(m0 + r0) * LSEQ + kc + c0);
        cp16(bb + 10240 + s1, LlB + (size_t)(m0 + r0 + 64) * LSEQ + kc + c0);
        uint32_t vb = VB + buf * 10240;
        cp16(vb + s0, Vhp + (size_t)r0 * LSEQ + kc + c0);
        cp16(vb + 5120 + s0, Vlp + (size_t)r0 * LSEQ + kc + c0);
        CP_COMMIT();
    };

    float accO[2][4][4];
#pragma unroll
    for (int mi = 0; mi < 2; mi++)
#pragma unroll
        for (int ni = 0; ni < 4; ni++)
#pragma unroll
            for (int j = 0; j < 4; j++) accO[mi][ni][j] = 0.f;

    issueL(0, 0);
    for (int it = 0; it < 32; it++) {
        if (it + 1 < 32) { issueL(it + 1, (it + 1) & 1); CP_WAIT1(); }
        else CP_WAIT0();
        __syncthreads();
        // transform logits -> probabilities (in place)
        {
            int bo = (it & 1) * 20480;
            xform_cell(dsm + bo + s0, dsm + bo + 10240 + s0, m_s[r0], s_s[r0]);
            xform_cell(dsm + bo + s1, dsm + bo + 10240 + s1, m_s[r0 + 64], s_s[r0 + 64]);
        }
        __syncthreads();
        uint32_t lb = base + (it & 1) * 20480;
        uint32_t vb = VB + (it & 1) * 10240;
        mma_pass<4>(lb, lb + 10240, vb, vb + 5120, wm, wnh * 32, lane, accO);
        __syncthreads();
    }

    // output epilogue (bf16 hi/lo for proj)
#pragma unroll
    for (int mi = 0; mi < 2; mi++)
#pragma unroll
        for (int ni = 0; ni < 4; ni++) {
            int row = m0 + wm + mi * 16 + (lane >> 2);
            int col = wnh * 32 + ni * 8 + (lane & 3) * 2;
#pragma unroll
            for (int half = 0; half < 2; half++) {
                int r = row + half * 8;
                float v0 = accO[mi][ni][2 * half], v1 = accO[mi][ni][2 * half + 1];
                __nv_bfloat16 h0, h1, l0, l1;
                split2(v0, h0, l0); split2(v1, h1, l1);
                __nv_bfloat162 hp = {h0, h1}, lp = {l0, l1};
                size_t e = ((size_t)(b * LSEQ + r)) * DIM + n * HD + col;
                *(uint32_t*)&OutH[e] = *(uint32_t*)&hp;
                *(uint32_t*)&OutL[e] = *(uint32_t*)&lp;
            }
        }
}

// ================= split qkv + 2D axial RoPE ====================================
__global__ __launch_bounds__(256) void rope_split_kernel(
    const float* __restrict__ qkv, float* __restrict__ qf,
    __nv_bfloat16* __restrict__ qh, __nv_bfloat16* __restrict__ ql,
    __nv_bfloat16* __restrict__ kh, __nv_bfloat16* __restrict__ kl)
{
    int idx = blockIdx.x * blockDim.x + threadIdx.x;
    const int TOT = NHEADS * LSEQ * (HD / 2);
    if (idx >= TOT) return;
    int j = idx & 31;
    int l = (idx >> 5) & (LSEQ - 1);
    int n = (idx >> 15) % NH;
    int b = idx / (32 * LSEQ * NH);

    size_t in_base = ((size_t)(b * LSEQ + l)) * NQKV + n * HD + 2 * j;
    size_t out_base = ((size_t)((b * NH + n) * LSEQ + l)) * HD + 2 * j;

    int i = j & 15;
    float pos = (j < 16) ? (float)(l & 31) : (float)(l >> 5);
    float f = exp2f(-(float)i * (13.287712379549449f / 16.0f));
    float sn, cs;
    sincosf(pos * f, &sn, &cs);

    float2 qa = *(const float2*)&qkv[in_base];
    float2 ka = *(const float2*)&qkv[in_base + DIM];
    float2 qo, ko;
    qo.x = qa.x * cs - qa.y * sn; qo.y = qa.x * sn + qa.y * cs;
    ko.x = ka.x * cs - ka.y * sn; ko.y = ka.x * sn + ka.y * cs;

    *(float2*)&qf[out_base] = qo;
    __nv_bfloat16 h0, h1, l0, l1;
    split2(qo.x, h0, l0); split2(qo.y, h1, l1);
    __nv_bfloat162 qhp = {h0, h1}, qlp = {l0, l1};
    *(uint32_t*)&qh[out_base] = *(uint32_t*)&qhp;
    *(uint32_t*)&ql[out_base] = *(uint32_t*)&qlp;
    split2(ko.x, h0, l0); split2(ko.y, h1, l1);
    __nv_bfloat162 khp = {h0, h1}, klp = {l0, l1};
    *(uint32_t*)&kh[out_base] = *(uint32_t*)&khp;
    *(uint32_t*)&kl[out_base] = *(uint32_t*)&klp;
}

// ================= V transpose -> bf16 hi/lo ====================================
__global__ __launch_bounds__(256) void vtrans_kernel(
    const float* __restrict__ qkv, __nv_bfloat16* __restrict__ Vth,
    __nv_bfloat16* __restrict__ Vtl)
{
    __shared__ float s[32][33];
    int bn = blockIdx.z, b = bn / NH, n = bn % NH;
    int l0 = blockIdx.x * 32, d0 = blockIdx.y * 32;
    int tx = threadIdx.x, ty = threadIdx.y;
#pragma unroll
    for (int i = 0; i < 32; i += 8)
        s[ty + i][tx] = qkv[(size_t)(b * LSEQ + l0 + ty + i) * NQKV + 2 * DIM + n * HD + d0 + tx];
    __syncthreads();
#pragma unroll
    for (int i = 0; i < 32; i += 8) {
        float v = s[tx][ty + i];
        __nv_bfloat16 h, l;
        split2(v, h, l);
        size_t e = (size_t)(bn * HD + d0 + ty + i) * LSEQ + l0 + tx;
        Vth[e] = h;
        Vtl[e] = l;
    }
}

// ================= rel-pos bias precompute ======================================
__global__ __launch_bounds__(256) void relbias_kernel(
    const float* __restrict__ Q, const float* __restrict__ rph,
    const float* __restrict__ rpw, float* __restrict__ RH, float* __restrict__ RW)
{
    __shared__ float qs[32][68];
    __shared__ float ts[32][68];
    const int bn = blockIdx.x;
    const int coord = blockIdx.y;
    const int mode = blockIdx.z;
    const int tid = threadIdx.x;

    {
        int r = tid >> 3;
        int c = (tid & 7) * 8;
        int l = (mode == 0) ? (coord * 32 + r) : (r * 32 + coord);
        const float* qrow = Q + ((size_t)bn * LSEQ + l) * HD;
        *(float4*)&qs[r][c]     = *(const float4*)&qrow[c];
        *(float4*)&qs[r][c + 4] = *(const float4*)&qrow[c + 4];
        const float* trow = ((mode == 0) ? rph : rpw) + (size_t)(coord - r + 31) * HD;
        *(float4*)&ts[r][c]     = *(const float4*)&trow[c];
        *(float4*)&ts[r][c + 4] = *(const float4*)&trow[c + 4];
    }
    __syncthreads();

    const int qq = tid >> 3;
    const int k0 = tid & 7;
    float acc[4] = {0.f, 0.f, 0.f, 0.f};
#pragma unroll
    for (int d = 0; d < HD; d += 4) {
        float4 q4 = *(const float4*)&qs[qq][d];
#pragma unroll
        for (int j = 0; j < 4; j++) {
            float4 t4 = *(const float4*)&ts[k0 + 8 * j][d];
            acc[j] = fmaf(q4.x, t4.x, fmaf(q4.y, t4.y,
                     fmaf(q4.z, t4.z, fmaf(q4.w, t4.w, acc[j]))));
        }
    }
    int lo = (mode == 0) ? (coord * 32 + qq) : (qq * 32 + coord);
    float* dst = ((mode == 0) ? RH : RW) + ((size_t)bn * LSEQ + lo) * 32;
#pragma unroll
    for (int j = 0; j < 4; j++) dst[k0 + 8 * j] = acc[j];
}

// ================= launch ========================================================
extern "C" void kernel_launch(void* const* d_in, const int* in_sizes, int n_in,
                              void* d_out, int out_size)
{
    const float* x      = (const float*)d_in[0];
    const float* qkv_w  = (const float*)d_in[1];
    const float* qkv_b  = (const float*)d_in[2];
    const float* proj_w = (const float*)d_in[3];
    const float* proj_b = (const float*)d_in[4];
    const float* rph    = (const float*)d_in[5];
    const float* rpw    = (const float*)d_in[6];
    float* out = (float*)d_out;

    float *p_qkv, *p_qf, *p_rh, *p_rw;
    __nv_bfloat16 *p_xh, *p_xl, *p_wqh, *p_wql, *p_ath, *p_atl, *p_wph, *p_wpl;
    __nv_bfloat16 *p_qh, *p_ql, *p_kh, *p_kl, *p_vth, *p_vtl, *p_Lh, *p_Ll;
    cudaGetSymbolAddress((void**)&p_qkv, g_qkv);
    cudaGetSymbolAddress((void**)&p_qf,  g_qf);
    cudaGetSymbolAddress((void**)&p_rh,  g_rh);
    cudaGetSymbolAddress((void**)&p_rw,  g_rw);
    cudaGetSymbolAddress((void**)&p_xh,  g_xh);
    cudaGetSymbolAddress((void**)&p_xl,  g_xl);
    cudaGetSymbolAddress((void**)&p_wqh, g_wqh);
    cudaGetSymbolAddress((void**)&p_wql, g_wql);
    cudaGetSymbolAddress((void**)&p_ath, g_ath);
    cudaGetSymbolAddress((void**)&p_atl, g_atl);
    cudaGetSymbolAddress((void**)&p_wph, g_wph);
    cudaGetSymbolAddress((void**)&p_wpl, g_wpl);
    cudaGetSymbolAddress((void**)&p_qh,  g_qh);
    cudaGetSymbolAddress((void**)&p_ql,  g_ql);
    cudaGetSymbolAddress((void**)&p_kh,  g_kh);
    cudaGetSymbolAddress((void**)&p_kl,  g_kl);
    cudaGetSymbolAddress((void**)&p_vth, g_vth);
    cudaGetSymbolAddress((void**)&p_vtl, g_vtl);
    cudaGetSymbolAddress((void**)&p_Lh,  g_Lh);
    cudaGetSymbolAddress((void**)&p_Ll,  g_Ll);

    const int GEMM_SMEM  = 2 * 4 * TILEB;   // 81920
    const int FLASH_SMEM = 81920;
    cudaFuncSetAttribute(mma_gemm, cudaFuncAttributeMaxDynamicSharedMemorySize, GEMM_SMEM);
    cudaFuncSetAttribute(flash_attn, cudaFuncAttributeMaxDynamicSharedMemorySize, FLASH_SMEM);

    // 0) bf16 splits of x and weights
    {
        int n4 = MROWS * DIM / 4;
        split_bf16<<<(n4 + 255) / 256, 256>>>((const float4*)x, (uint32_t*)p_xh,
                                              (uint32_t*)p_xl, n4);
        n4 = NQKV * DIM / 4;
        split_bf16<<<(n4 + 255) / 256, 256>>>((const float4*)qkv_w, (uint32_t*)p_wqh,
                                              (uint32_t*)p_wql, n4);
        n4 = DIM * DIM / 4;
        split_bf16<<<(n4 + 255) / 256, 256>>>((const float4*)proj_w, (uint32_t*)p_wph,
                                              (uint32_t*)p_wpl, n4);
    }

    // 1) QKV GEMM (HMMA)
    mma_gemm<<<dim3(NQKV / 128, MROWS / 128), 256, GEMM_SMEM>>>(
        p_xh, p_xl, p_wqh, p_wql, qkv_b, p_qkv, NQKV, DIM);

    // 2) split + rope
    {
        const int TOT = NHEADS * LSEQ * (HD / 2);
        rope_split_kernel<<<(TOT + 255) / 256, 256>>>(p_qkv, p_qf, p_qh, p_ql,
                                                      p_kh, p_kl);
    }

    // 3) V transpose
    vtrans_kernel<<<dim3(LSEQ / 32, HD / 32, NHEADS), dim3(32, 8)>>>(
        p_qkv, p_vth, p_vtl);

    // 4) rel-pos bias precompute
    relbias_kernel<<<dim3(NHEADS, 32, 2), 256>>>(p_qf, rph, rpw, p_rh, p_rw);

    // 5) fused attention (scores + softmax + AV)
    flash_attn<<<dim3(LSEQ / 128, NHEADS), 256, FLASH_SMEM>>>(
        p_qh, p_ql, p_kh, p_kl, p_vth, p_vtl, p_rh, p_rw,
        p_Lh, p_Ll, p_ath, p_atl);

    // 6) output projection (HMMA)
    mma_gemm<<<dim3(DIM / 128, MROWS / 128), 256, GEMM_SMEM>>>(
        p_ath, p_atl, p_wph, p_wpl, proj_b, out, DIM, DIM);
}